// round 1
// baseline (speedup 1.0000x reference)
#include <cuda_runtime.h>

// ---------------- problem constants ----------------
#define NMAX   50048      // padded node capacity
#define EMAX   800000
#define GMAX   64
#define HD     128        // hidden dim (H*D)
#define PW     512        // q|k|v|skip packed row width

// ---------------- static scratch (no allocs allowed) ----------------
__device__ float g_P[(size_t)NMAX * PW];      // packed projections q|k|v|s
__device__ float g_H0[(size_t)NMAX * HD];     // layer0 output (post relu)
__device__ float g_H1[(size_t)NMAX * HD];     // layer1 output (post relu)
__device__ int   g_deg[NMAX];
__device__ int   g_cnt[NMAX];
__device__ int   g_rowptr[NMAX + 1];
__device__ int   g_src[EMAX];
__device__ float g_attr[EMAX];
__device__ int   g_ghist[GMAX];
__device__ int   g_gstart[GMAX + 1];
__device__ float g_pool[GMAX * HD];

// ---------------- CSR build ----------------
__global__ void zero_kernel(int N) {
    int i = blockIdx.x * blockDim.x + threadIdx.x;
    if (i < N) { g_deg[i] = 0; g_cnt[i] = 0; }
    if (i < GMAX) g_ghist[i] = 0;
}

__global__ void hist_kernel(const int* __restrict__ dst,
                            const int* __restrict__ batch, int N, int E) {
    int i = blockIdx.x * blockDim.x + threadIdx.x;
    if (i < E) atomicAdd(&g_deg[dst[i]], 1);
    if (i < N) atomicAdd(&g_ghist[batch[i]], 1);
}

// single-block exclusive scan of g_deg -> g_rowptr; also g_ghist -> g_gstart
__global__ void scan_kernel(int N) {
    __shared__ int sums[1024];
    int t = threadIdx.x;
    int chunk = (N + 1023) >> 10;
    int lo = t * chunk;
    int hi = min(lo + chunk, N);
    int s = 0;
    for (int i = lo; i < hi; i++) s += g_deg[i];
    sums[t] = s;
    __syncthreads();
    // Hillis-Steele inclusive scan
    for (int off = 1; off < 1024; off <<= 1) {
        int v = (t >= off) ? sums[t - off] : 0;
        __syncthreads();
        sums[t] += v;
        __syncthreads();
    }
    int run = sums[t] - s;   // exclusive prefix
    for (int i = lo; i < hi; i++) { g_rowptr[i] = run; run += g_deg[i]; }
    if (t == 1023) g_rowptr[N] = sums[1023];
    if (t == 0) {
        int r = 0;
        for (int g = 0; g < GMAX; g++) { g_gstart[g] = r; r += g_ghist[g]; }
        g_gstart[GMAX] = r;
    }
}

__global__ void scatter_kernel(const int* __restrict__ src,
                               const int* __restrict__ dst,
                               const float* __restrict__ attr, int E) {
    int i = blockIdx.x * blockDim.x + threadIdx.x;
    if (i >= E) return;
    int d = dst[i];
    int p = g_rowptr[d] + atomicAdd(&g_cnt[d], 1);
    g_src[p]  = src[i];
    g_attr[p] = attr[i];
}

// ---------------- layer-0 projections (in_ch = 2) ----------------
__global__ void proj0_kernel(const float* __restrict__ x,
                             const float* __restrict__ Wq, const float* __restrict__ bq,
                             const float* __restrict__ Wk, const float* __restrict__ bk,
                             const float* __restrict__ Wv, const float* __restrict__ bv,
                             const float* __restrict__ Ws, const float* __restrict__ bs,
                             int N) {
    int idx = blockIdx.x * blockDim.x + threadIdx.x;     // one float4 of P
    if (idx >= N * 128) return;
    int n  = idx >> 7;
    int c4 = idx & 127;            // float4 index within 512-wide row
    int sel = c4 >> 5;             // 0=q 1=k 2=v 3=skip
    int cc  = (c4 & 31) * 4;       // column within 128
    const float* W; const float* b;
    if (sel == 0)      { W = Wq; b = bq; }
    else if (sel == 1) { W = Wk; b = bk; }
    else if (sel == 2) { W = Wv; b = bv; }
    else               { W = Ws; b = bs; }
    float x0 = x[2 * n], x1 = x[2 * n + 1];
    float4 w0 = *(const float4*)(W + cc);        // W[0, cc..]
    float4 w1 = *(const float4*)(W + 128 + cc);  // W[1, cc..]
    float4 bb = *(const float4*)(b + cc);
    float4 r;
    r.x = fmaf(x0, w0.x, fmaf(x1, w1.x, bb.x));
    r.y = fmaf(x0, w0.y, fmaf(x1, w1.y, bb.y));
    r.z = fmaf(x0, w0.z, fmaf(x1, w1.z, bb.z));
    r.w = fmaf(x0, w0.w, fmaf(x1, w1.w, bb.w));
    ((float4*)g_P)[(size_t)n * 128 + c4] = r;
}

// ---------------- layer-1 projections: SGEMM [N,128] x [128,128] ----------------
// BM=128 BN=128 BK=8, 256 threads, 8x8 micro-tile. A = g_H0, writes into g_P at colOff.
__global__ __launch_bounds__(256) void gemm_proj(const float* __restrict__ W,
                                                 const float* __restrict__ bias,
                                                 int M, int colOff) {
    __shared__ float As[8][128];
    __shared__ float Bs[8][128];
    int tid = threadIdx.x;
    int tx = tid & 15, ty = tid >> 4;
    int blockM = blockIdx.x * 128;

    float acc[8][8];
#pragma unroll
    for (int i = 0; i < 8; i++)
#pragma unroll
        for (int j = 0; j < 8; j++) acc[i][j] = 0.f;

    int aRow = tid >> 1;            // 0..127
    int aCol = (tid & 1) * 4;       // 0 or 4
    int bRow = tid >> 5;            // 0..7
    int bCol = (tid & 31) * 4;      // 0..124
    bool aValid = (blockM + aRow) < M;
    const float* Ag = g_H0 + (size_t)(blockM + aRow) * HD + aCol;

    for (int k0 = 0; k0 < 128; k0 += 8) {
        float4 av = aValid ? *(const float4*)(Ag + k0) : make_float4(0.f, 0.f, 0.f, 0.f);
        float4 bv = *(const float4*)(W + (size_t)(k0 + bRow) * 128 + bCol);
        As[aCol + 0][aRow] = av.x;
        As[aCol + 1][aRow] = av.y;
        As[aCol + 2][aRow] = av.z;
        As[aCol + 3][aRow] = av.w;
        *(float4*)(&Bs[bRow][bCol]) = bv;
        __syncthreads();
#pragma unroll
        for (int kk = 0; kk < 8; kk++) {
            float ar[8], br[8];
#pragma unroll
            for (int i = 0; i < 8; i++) ar[i] = As[kk][ty * 8 + i];
#pragma unroll
            for (int j = 0; j < 8; j++) br[j] = Bs[kk][tx * 8 + j];
#pragma unroll
            for (int i = 0; i < 8; i++)
#pragma unroll
                for (int j = 0; j < 8; j++) acc[i][j] = fmaf(ar[i], br[j], acc[i][j]);
        }
        __syncthreads();
    }

    float4 bb0 = *(const float4*)(bias + tx * 8);
    float4 bb1 = *(const float4*)(bias + tx * 8 + 4);
#pragma unroll
    for (int i = 0; i < 8; i++) {
        int row = blockM + ty * 8 + i;
        if (row < M) {
            float4 o0 = make_float4(acc[i][0] + bb0.x, acc[i][1] + bb0.y,
                                    acc[i][2] + bb0.z, acc[i][3] + bb0.w);
            float4 o1 = make_float4(acc[i][4] + bb1.x, acc[i][5] + bb1.y,
                                    acc[i][6] + bb1.z, acc[i][7] + bb1.w);
            float* dstp = g_P + (size_t)row * PW + colOff + tx * 8;
            *(float4*)(dstp)     = o0;
            *(float4*)(dstp + 4) = o1;
        }
    }
}

// ---------------- edge attention: one warp per node, online softmax ----------------
// P row layout (float4 units, 128 per row): q:0..31  k:32..63  v:64..95  s:96..127
__global__ void attn_kernel(const float* __restrict__ We, int which, int N) {
    int gt   = blockIdx.x * blockDim.x + threadIdx.x;
    int lane = threadIdx.x & 31;
    int n    = gt >> 5;
    if (n >= N) return;

    const float4* P4 = (const float4*)g_P;
    size_t base = (size_t)n * 128;
    float4 qv = P4[base + lane];
    float4 we = ((const float4*)We)[lane];

    float4 acc = make_float4(0.f, 0.f, 0.f, 0.f);
    float m = -1e30f;
    float den = 0.f;

    int beg = g_rowptr[n], end = g_rowptr[n + 1];
    for (int i = beg; i < end; i++) {
        int   s = g_src[i];
        float a = g_attr[i];
        size_t sb = (size_t)s * 128;
        float4 kk = P4[sb + 32 + lane];
        kk.x = fmaf(a, we.x, kk.x);
        kk.y = fmaf(a, we.y, kk.y);
        kk.z = fmaf(a, we.z, kk.z);
        kk.w = fmaf(a, we.w, kk.w);
        float part = qv.x * kk.x + qv.y * kk.y + qv.z * kk.z + qv.w * kk.w;
        // reduce within 16-lane head segment
        part += __shfl_xor_sync(0xffffffffu, part, 8, 16);
        part += __shfl_xor_sync(0xffffffffu, part, 4, 16);
        part += __shfl_xor_sync(0xffffffffu, part, 2, 16);
        part += __shfl_xor_sync(0xffffffffu, part, 1, 16);
        float logit = part * 0.125f;      // / sqrt(64)

        float nm    = fmaxf(m, logit);
        float scale = __expf(m - nm);
        float ex    = __expf(logit - nm);

        float4 vv = P4[sb + 64 + lane];
        vv.x = fmaf(a, we.x, vv.x);
        vv.y = fmaf(a, we.y, vv.y);
        vv.z = fmaf(a, we.z, vv.z);
        vv.w = fmaf(a, we.w, vv.w);

        acc.x = fmaf(acc.x, scale, ex * vv.x);
        acc.y = fmaf(acc.y, scale, ex * vv.y);
        acc.z = fmaf(acc.z, scale, ex * vv.z);
        acc.w = fmaf(acc.w, scale, ex * vv.w);
        den = fmaf(den, scale, ex);
        m = nm;
    }

    float inv = 1.f / (den + 1e-16f);
    float4 sk = P4[base + 96 + lane];
    float4 o;
    o.x = fmaxf(fmaf(acc.x, inv, sk.x), 0.f);
    o.y = fmaxf(fmaf(acc.y, inv, sk.y), 0.f);
    o.z = fmaxf(fmaf(acc.z, inv, sk.z), 0.f);
    o.w = fmaxf(fmaf(acc.w, inv, sk.w), 0.f);
    float* H = which ? g_H1 : g_H0;
    ((float4*)H)[(size_t)n * 32 + lane] = o;
}

// ---------------- graph mean pool (batch is sorted) ----------------
__global__ void pool_kernel() {
    int g = blockIdx.x;
    int t = threadIdx.x;
    int b0 = g_gstart[g], b1 = g_gstart[g + 1];
    float acc = 0.f;
#pragma unroll 4
    for (int n = b0; n < b1; n++) acc += g_H1[(size_t)n * HD + t];
    float c = (float)max(b1 - b0, 1);
    g_pool[g * HD + t] = acc / c;
}

// ---------------- classifier head: relu(g@cW1+cb1)@cW2+cb2 ----------------
__global__ void classifier_kernel(const float* __restrict__ cW1, const float* __restrict__ cb1,
                                  const float* __restrict__ cW2, const float* __restrict__ cb2,
                                  float* __restrict__ out) {
    __shared__ float gs[HD];
    __shared__ float hid[HD];
    int g = blockIdx.x;
    int t = threadIdx.x;
    gs[t] = g_pool[g * HD + t];
    __syncthreads();
    float acc = cb1[t];
#pragma unroll 8
    for (int c = 0; c < HD; c++) acc = fmaf(gs[c], cW1[c * 128 + t], acc);
    hid[t] = fmaxf(acc, 0.f);
    __syncthreads();
    if (t < 30) {
        float o = cb2[t];
#pragma unroll 8
        for (int j = 0; j < HD; j++) o = fmaf(hid[j], cW2[j * 30 + t], o);
        out[g * 30 + t] = o;
    }
}

// ---------------- launch ----------------
extern "C" void kernel_launch(void* const* d_in, const int* in_sizes, int n_in,
                              void* d_out, int out_size) {
    const float* x      = (const float*)d_in[0];
    const int*   ei     = (const int*)d_in[1];
    const float* eattr  = (const float*)d_in[2];
    const int*   batch  = (const int*)d_in[3];
    const float* l0_Wq = (const float*)d_in[4];
    const float* l0_bq = (const float*)d_in[5];
    const float* l0_Wk = (const float*)d_in[6];
    const float* l0_bk = (const float*)d_in[7];
    const float* l0_Wv = (const float*)d_in[8];
    const float* l0_bv = (const float*)d_in[9];
    const float* l0_We = (const float*)d_in[10];
    const float* l0_Ws = (const float*)d_in[11];
    const float* l0_bs = (const float*)d_in[12];
    const float* l1_Wq = (const float*)d_in[13];
    const float* l1_bq = (const float*)d_in[14];
    const float* l1_Wk = (const float*)d_in[15];
    const float* l1_bk = (const float*)d_in[16];
    const float* l1_Wv = (const float*)d_in[17];
    const float* l1_bv = (const float*)d_in[18];
    const float* l1_We = (const float*)d_in[19];
    const float* l1_Ws = (const float*)d_in[20];
    const float* l1_bs = (const float*)d_in[21];
    const float* cW1   = (const float*)d_in[22];
    const float* cb1   = (const float*)d_in[23];
    const float* cW2   = (const float*)d_in[24];
    const float* cb2   = (const float*)d_in[25];
    float* out = (float*)d_out;

    int N = in_sizes[3];       // batch length = #nodes
    int E = in_sizes[2];       // edge_attr length = #edges
    const int* src = ei;
    const int* dst = ei + E;

    // CSR build (reused by both layers)
    zero_kernel<<<(N + 255) / 256, 256>>>(N);
    hist_kernel<<<(E + 255) / 256, 256>>>(dst, batch, N, E);
    scan_kernel<<<1, 1024>>>(N);
    scatter_kernel<<<(E + 255) / 256, 256>>>(src, dst, eattr, E);

    // layer 0
    proj0_kernel<<<(N * 128 + 255) / 256, 256>>>(x, l0_Wq, l0_bq, l0_Wk, l0_bk,
                                                 l0_Wv, l0_bv, l0_Ws, l0_bs, N);
    attn_kernel<<<(N * 32 + 255) / 256, 256>>>(l0_We, 0, N);

    // layer 1 projections: 4 GEMMs into packed P
    int gblocks = (N + 127) / 128;
    gemm_proj<<<gblocks, 256>>>(l1_Wq, l1_bq, N, 0);
    gemm_proj<<<gblocks, 256>>>(l1_Wk, l1_bk, N, 128);
    gemm_proj<<<gblocks, 256>>>(l1_Wv, l1_bv, N, 256);
    gemm_proj<<<gblocks, 256>>>(l1_Ws, l1_bs, N, 384);

    attn_kernel<<<(N * 32 + 255) / 256, 256>>>(l1_We, 1, N);

    // pool + head
    pool_kernel<<<GMAX, HD>>>();
    classifier_kernel<<<GMAX, HD>>>(cW1, cb1, cW2, cb2, out);
}

// round 2
// speedup vs baseline: 1.1686x; 1.1686x over previous
#include <cuda_runtime.h>
#include <cstdint>

// ---------------- problem constants ----------------
#define NMAX   50048      // padded node capacity
#define EMAX   800000
#define GMAX   64
#define HD     128        // hidden dim (H*D)
#define PW     512        // q|k|v|skip packed row width

// ---------------- static scratch (no allocs allowed) ----------------
__device__ float g_P[(size_t)NMAX * PW];      // packed projections q|k|v|s
__device__ float g_H0[(size_t)NMAX * HD];     // layer0 output (post relu)
__device__ float g_H1[(size_t)NMAX * HD];     // layer1 output (post relu)
__device__ int   g_deg[NMAX];
__device__ int   g_cnt[NMAX];
__device__ int   g_rowptr[NMAX + 1];
__device__ int   g_src[EMAX];
__device__ float g_attr[EMAX];
__device__ int   g_ghist[GMAX];
__device__ int   g_gstart[GMAX + 1];
__device__ float g_pool[GMAX * HD];

// ---------------- CSR build ----------------
__global__ void zero_kernel(int N) {
    int i = blockIdx.x * blockDim.x + threadIdx.x;
    if (i < N) { g_deg[i] = 0; g_cnt[i] = 0; }
    if (i < GMAX) g_ghist[i] = 0;
}

__global__ void hist_kernel(const int* __restrict__ dst,
                            const int* __restrict__ batch, int N, int E) {
    int i = blockIdx.x * blockDim.x + threadIdx.x;
    if (i < E) atomicAdd(&g_deg[dst[i]], 1);
    if (i < N) atomicAdd(&g_ghist[batch[i]], 1);
}

// single-block exclusive scan of g_deg -> g_rowptr; also g_ghist -> g_gstart
__global__ void scan_kernel(int N) {
    __shared__ int sums[1024];
    int t = threadIdx.x;
    int chunk = (N + 1023) >> 10;
    int lo = t * chunk;
    int hi = min(lo + chunk, N);
    int s = 0;
    for (int i = lo; i < hi; i++) s += g_deg[i];
    sums[t] = s;
    __syncthreads();
    for (int off = 1; off < 1024; off <<= 1) {
        int v = (t >= off) ? sums[t - off] : 0;
        __syncthreads();
        sums[t] += v;
        __syncthreads();
    }
    int run = sums[t] - s;   // exclusive prefix
    for (int i = lo; i < hi; i++) { g_rowptr[i] = run; run += g_deg[i]; }
    if (t == 1023) g_rowptr[N] = sums[1023];
    if (t == 0) {
        int r = 0;
        for (int g = 0; g < GMAX; g++) { g_gstart[g] = r; r += g_ghist[g]; }
        g_gstart[GMAX] = r;
    }
}

__global__ void scatter_kernel(const int* __restrict__ src,
                               const int* __restrict__ dst,
                               const float* __restrict__ attr, int E) {
    int i = blockIdx.x * blockDim.x + threadIdx.x;
    if (i >= E) return;
    int d = dst[i];
    int p = g_rowptr[d] + atomicAdd(&g_cnt[d], 1);
    g_src[p]  = src[i];
    g_attr[p] = attr[i];
}

// ---------------- layer-0 projections (in_ch = 2) ----------------
__global__ void proj0_kernel(const float* __restrict__ x,
                             const float* __restrict__ Wq, const float* __restrict__ bq,
                             const float* __restrict__ Wk, const float* __restrict__ bk,
                             const float* __restrict__ Wv, const float* __restrict__ bv,
                             const float* __restrict__ Ws, const float* __restrict__ bs,
                             int N) {
    int idx = blockIdx.x * blockDim.x + threadIdx.x;     // one float4 of P
    if (idx >= N * 128) return;
    int n  = idx >> 7;
    int c4 = idx & 127;            // float4 index within 512-wide row
    int sel = c4 >> 5;             // 0=q 1=k 2=v 3=skip
    int cc  = (c4 & 31) * 4;       // column within 128
    const float* W; const float* b;
    if (sel == 0)      { W = Wq; b = bq; }
    else if (sel == 1) { W = Wk; b = bk; }
    else if (sel == 2) { W = Wv; b = bv; }
    else               { W = Ws; b = bs; }
    float x0 = x[2 * n], x1 = x[2 * n + 1];
    float4 w0 = *(const float4*)(W + cc);        // W[0, cc..]
    float4 w1 = *(const float4*)(W + 128 + cc);  // W[1, cc..]
    float4 bb = *(const float4*)(b + cc);
    float4 r;
    r.x = fmaf(x0, w0.x, fmaf(x1, w1.x, bb.x));
    r.y = fmaf(x0, w0.y, fmaf(x1, w1.y, bb.y));
    r.z = fmaf(x0, w0.z, fmaf(x1, w1.z, bb.z));
    r.w = fmaf(x0, w0.w, fmaf(x1, w1.w, bb.w));
    ((float4*)g_P)[(size_t)n * 128 + c4] = r;
}

// ---------------- layer-1 projections: 3xTF32 tensor-core GEMM ----------------
// P[:, sec*128 : sec*128+128] = H0[N,128] @ W_sec[128,128] + b_sec
// grid = (ceil(N/128), 4), 256 threads (8 warps), warp tile 64x32, mma m16n8k8.
#define SA 20     // A smem panel stride (16 + 4 pad)  -> conflict-free frag loads
#define SB 136    // B smem panel stride (128 + 8 pad) -> conflict-free frag loads

__device__ __forceinline__ void split_tf32(float x, uint32_t& hi, uint32_t& lo) {
    uint32_t h;
    asm("cvt.rna.tf32.f32 %0, %1;" : "=r"(h) : "f"(x));
    float r = x - __uint_as_float(h);
    uint32_t l;
    asm("cvt.rna.tf32.f32 %0, %1;" : "=r"(l) : "f"(r));
    hi = h; lo = l;
}

__device__ __forceinline__ void mma8(float* c, const uint32_t* a, const uint32_t* b) {
    asm volatile(
        "mma.sync.aligned.m16n8k8.row.col.f32.tf32.tf32.f32 "
        "{%0,%1,%2,%3}, {%4,%5,%6,%7}, {%8,%9}, {%0,%1,%2,%3};"
        : "+f"(c[0]), "+f"(c[1]), "+f"(c[2]), "+f"(c[3])
        : "r"(a[0]), "r"(a[1]), "r"(a[2]), "r"(a[3]), "r"(b[0]), "r"(b[1]));
}

__global__ __launch_bounds__(256, 2) void gemm3_kernel(
    const float* __restrict__ Wq, const float* __restrict__ Wk,
    const float* __restrict__ Wv, const float* __restrict__ Ws,
    const float* __restrict__ bq, const float* __restrict__ bk,
    const float* __restrict__ bv, const float* __restrict__ bs) {
    __shared__ uint32_t AsH[128][SA];
    __shared__ uint32_t AsL[128][SA];
    __shared__ uint32_t BsH[16][SB];
    __shared__ uint32_t BsL[16][SB];

    const float* W; const float* bias;
    int sec = blockIdx.y;
    if (sec == 0)      { W = Wq; bias = bq; }
    else if (sec == 1) { W = Wk; bias = bk; }
    else if (sec == 2) { W = Wv; bias = bv; }
    else               { W = Ws; bias = bs; }

    int tid  = threadIdx.x;
    int warp = tid >> 5, lane = tid & 31;
    int g    = lane >> 2, tig = lane & 3;
    int wm   = warp >> 2, wn = warp & 3;         // 2 x 4 warp grid
    int blockM = blockIdx.x * 128;

    float acc[4][4][4];
#pragma unroll
    for (int mt = 0; mt < 4; mt++)
#pragma unroll
        for (int nt = 0; nt < 4; nt++)
#pragma unroll
            for (int c = 0; c < 4; c++) acc[mt][nt][c] = 0.f;

#pragma unroll 1
    for (int kp = 0; kp < 8; kp++) {
        int k0 = kp * 16;
        __syncthreads();
        // load A panel: 128 rows x 16 cols = 512 float4 (2 per thread)
#pragma unroll
        for (int j = 0; j < 2; j++) {
            int pos = tid + 256 * j;
            int row = pos >> 2;
            int c4  = pos & 3;
            float4 v = *(const float4*)(g_H0 + (size_t)(blockM + row) * 128 + k0 + c4 * 4);
            uint4 h, l;
            split_tf32(v.x, h.x, l.x);
            split_tf32(v.y, h.y, l.y);
            split_tf32(v.z, h.z, l.z);
            split_tf32(v.w, h.w, l.w);
            *(uint4*)&AsH[row][c4 * 4] = h;
            *(uint4*)&AsL[row][c4 * 4] = l;
        }
        // load B panel: 16 rows x 128 cols = 512 float4 (2 per thread)
#pragma unroll
        for (int j = 0; j < 2; j++) {
            int pos = tid + 256 * j;
            int row = pos >> 5;
            int c4  = pos & 31;
            float4 v = *(const float4*)(W + (size_t)(k0 + row) * 128 + c4 * 4);
            uint4 h, l;
            split_tf32(v.x, h.x, l.x);
            split_tf32(v.y, h.y, l.y);
            split_tf32(v.z, h.z, l.z);
            split_tf32(v.w, h.w, l.w);
            *(uint4*)&BsH[row][c4 * 4] = h;
            *(uint4*)&BsL[row][c4 * 4] = l;
        }
        __syncthreads();

#pragma unroll
        for (int ks = 0; ks < 2; ks++) {
            int kk = ks * 8;
            uint32_t bh[4][2], bl[4][2];
#pragma unroll
            for (int nt = 0; nt < 4; nt++) {
                int col = wn * 32 + nt * 8 + g;
                bh[nt][0] = BsH[kk + tig][col];
                bh[nt][1] = BsH[kk + tig + 4][col];
                bl[nt][0] = BsL[kk + tig][col];
                bl[nt][1] = BsL[kk + tig + 4][col];
            }
#pragma unroll
            for (int mt = 0; mt < 4; mt++) {
                int r0 = wm * 64 + mt * 16 + g;
                uint32_t ah[4], al[4];
                ah[0] = AsH[r0][kk + tig];
                ah[1] = AsH[r0 + 8][kk + tig];
                ah[2] = AsH[r0][kk + tig + 4];
                ah[3] = AsH[r0 + 8][kk + tig + 4];
                al[0] = AsL[r0][kk + tig];
                al[1] = AsL[r0 + 8][kk + tig];
                al[2] = AsL[r0][kk + tig + 4];
                al[3] = AsL[r0 + 8][kk + tig + 4];
#pragma unroll
                for (int nt = 0; nt < 4; nt++) {
                    mma8(acc[mt][nt], ah, bh[nt]);   // hi*hi
                    mma8(acc[mt][nt], ah, bl[nt]);   // hi*lo
                    mma8(acc[mt][nt], al, bh[nt]);   // lo*hi
                }
            }
        }
    }

    // store with bias into packed P
    int secOff = sec * 128;
#pragma unroll
    for (int mt = 0; mt < 4; mt++) {
        int r0 = blockM + wm * 64 + mt * 16 + g;
#pragma unroll
        for (int nt = 0; nt < 4; nt++) {
            int cn = wn * 32 + nt * 8 + tig * 2;
            float b0 = bias[cn], b1 = bias[cn + 1];
            float2 v0 = make_float2(acc[mt][nt][0] + b0, acc[mt][nt][1] + b1);
            float2 v1 = make_float2(acc[mt][nt][2] + b0, acc[mt][nt][3] + b1);
            *(float2*)(g_P + (size_t)r0 * PW + secOff + cn)       = v0;
            *(float2*)(g_P + (size_t)(r0 + 8) * PW + secOff + cn) = v1;
        }
    }
}

// ---------------- edge attention: one warp per node, online softmax ----------------
// P row layout (float4 units, 128 per row): q:0..31  k:32..63  v:64..95  s:96..127
__global__ void attn_kernel(const float* __restrict__ We, int which, int N) {
    int gt   = blockIdx.x * blockDim.x + threadIdx.x;
    int lane = threadIdx.x & 31;
    int n    = gt >> 5;
    if (n >= N) return;

    const float4* P4 = (const float4*)g_P;
    size_t base = (size_t)n * 128;
    float4 qv = P4[base + lane];
    float4 we = ((const float4*)We)[lane];

    float4 acc = make_float4(0.f, 0.f, 0.f, 0.f);
    float m = -1e30f;
    float den = 0.f;

    int beg = g_rowptr[n], end = g_rowptr[n + 1];
    for (int i = beg; i < end; i++) {
        int   s = g_src[i];
        float a = g_attr[i];
        size_t sb = (size_t)s * 128;
        float4 kk = P4[sb + 32 + lane];
        kk.x = fmaf(a, we.x, kk.x);
        kk.y = fmaf(a, we.y, kk.y);
        kk.z = fmaf(a, we.z, kk.z);
        kk.w = fmaf(a, we.w, kk.w);
        float part = qv.x * kk.x + qv.y * kk.y + qv.z * kk.z + qv.w * kk.w;
        part += __shfl_xor_sync(0xffffffffu, part, 8, 16);
        part += __shfl_xor_sync(0xffffffffu, part, 4, 16);
        part += __shfl_xor_sync(0xffffffffu, part, 2, 16);
        part += __shfl_xor_sync(0xffffffffu, part, 1, 16);
        float logit = part * 0.125f;      // / sqrt(64)

        float nm    = fmaxf(m, logit);
        float scale = __expf(m - nm);
        float ex    = __expf(logit - nm);

        float4 vv = P4[sb + 64 + lane];
        vv.x = fmaf(a, we.x, vv.x);
        vv.y = fmaf(a, we.y, vv.y);
        vv.z = fmaf(a, we.z, vv.z);
        vv.w = fmaf(a, we.w, vv.w);

        acc.x = fmaf(acc.x, scale, ex * vv.x);
        acc.y = fmaf(acc.y, scale, ex * vv.y);
        acc.z = fmaf(acc.z, scale, ex * vv.z);
        acc.w = fmaf(acc.w, scale, ex * vv.w);
        den = fmaf(den, scale, ex);
        m = nm;
    }

    float inv = 1.f / (den + 1e-16f);
    float4 sk = P4[base + 96 + lane];
    float4 o;
    o.x = fmaxf(fmaf(acc.x, inv, sk.x), 0.f);
    o.y = fmaxf(fmaf(acc.y, inv, sk.y), 0.f);
    o.z = fmaxf(fmaf(acc.z, inv, sk.z), 0.f);
    o.w = fmaxf(fmaf(acc.w, inv, sk.w), 0.f);
    float* H = which ? g_H1 : g_H0;
    ((float4*)H)[(size_t)n * 32 + lane] = o;
}

// ---------------- graph mean pool (batch is sorted) ----------------
__global__ void pool_kernel() {
    int g = blockIdx.x;
    int t = threadIdx.x;
    int b0 = g_gstart[g], b1 = g_gstart[g + 1];
    float acc = 0.f;
#pragma unroll 4
    for (int n = b0; n < b1; n++) acc += g_H1[(size_t)n * HD + t];
    float c = (float)max(b1 - b0, 1);
    g_pool[g * HD + t] = acc / c;
}

// ---------------- classifier head: relu(g@cW1+cb1)@cW2+cb2 ----------------
__global__ void classifier_kernel(const float* __restrict__ cW1, const float* __restrict__ cb1,
                                  const float* __restrict__ cW2, const float* __restrict__ cb2,
                                  float* __restrict__ out) {
    __shared__ float gs[HD];
    __shared__ float hid[HD];
    int g = blockIdx.x;
    int t = threadIdx.x;
    gs[t] = g_pool[g * HD + t];
    __syncthreads();
    float acc = cb1[t];
#pragma unroll 8
    for (int c = 0; c < HD; c++) acc = fmaf(gs[c], cW1[c * 128 + t], acc);
    hid[t] = fmaxf(acc, 0.f);
    __syncthreads();
    if (t < 30) {
        float o = cb2[t];
#pragma unroll 8
        for (int j = 0; j < HD; j++) o = fmaf(hid[j], cW2[j * 30 + t], o);
        out[g * 30 + t] = o;
    }
}

// ---------------- launch ----------------
extern "C" void kernel_launch(void* const* d_in, const int* in_sizes, int n_in,
                              void* d_out, int out_size) {
    const float* x      = (const float*)d_in[0];
    const int*   ei     = (const int*)d_in[1];
    const float* eattr  = (const float*)d_in[2];
    const int*   batch  = (const int*)d_in[3];
    const float* l0_Wq = (const float*)d_in[4];
    const float* l0_bq = (const float*)d_in[5];
    const float* l0_Wk = (const float*)d_in[6];
    const float* l0_bk = (const float*)d_in[7];
    const float* l0_Wv = (const float*)d_in[8];
    const float* l0_bv = (const float*)d_in[9];
    const float* l0_We = (const float*)d_in[10];
    const float* l0_Ws = (const float*)d_in[11];
    const float* l0_bs = (const float*)d_in[12];
    const float* l1_Wq = (const float*)d_in[13];
    const float* l1_bq = (const float*)d_in[14];
    const float* l1_Wk = (const float*)d_in[15];
    const float* l1_bk = (const float*)d_in[16];
    const float* l1_Wv = (const float*)d_in[17];
    const float* l1_bv = (const float*)d_in[18];
    const float* l1_We = (const float*)d_in[19];
    const float* l1_Ws = (const float*)d_in[20];
    const float* l1_bs = (const float*)d_in[21];
    const float* cW1   = (const float*)d_in[22];
    const float* cb1   = (const float*)d_in[23];
    const float* cW2   = (const float*)d_in[24];
    const float* cb2   = (const float*)d_in[25];
    float* out = (float*)d_out;

    int N = in_sizes[3];       // batch length = #nodes
    int E = in_sizes[2];       // edge_attr length = #edges
    const int* src = ei;
    const int* dst = ei + E;

    // CSR build (reused by both layers)
    zero_kernel<<<(N + 255) / 256, 256>>>(N);
    hist_kernel<<<(E + 255) / 256, 256>>>(dst, batch, N, E);
    scan_kernel<<<1, 1024>>>(N);
    scatter_kernel<<<(E + 255) / 256, 256>>>(src, dst, eattr, E);

    // layer 0
    proj0_kernel<<<(N * 128 + 255) / 256, 256>>>(x, l0_Wq, l0_bq, l0_Wk, l0_bk,
                                                 l0_Wv, l0_bv, l0_Ws, l0_bs, N);
    attn_kernel<<<(N * 32 + 255) / 256, 256>>>(l0_We, 0, N);

    // layer 1 projections: fused 3xTF32 tensor-core GEMM, all 4 weights
    dim3 ggrid((N + 127) / 128, 4);
    gemm3_kernel<<<ggrid, 256>>>(l1_Wq, l1_Wk, l1_Wv, l1_Ws,
                                 l1_bq, l1_bk, l1_bv, l1_bs);

    attn_kernel<<<(N * 32 + 255) / 256, 256>>>(l1_We, 1, N);

    // pool + head
    pool_kernel<<<GMAX, HD>>>();
    classifier_kernel<<<GMAX, HD>>>(cW1, cb1, cW2, cb2, out);
}

// round 3
// speedup vs baseline: 1.2173x; 1.0417x over previous
#include <cuda_runtime.h>
#include <cstdint>

// ---------------- problem constants ----------------
#define NMAX   50048      // padded node capacity
#define EMAX   800000
#define GMAX   64
#define HD     128        // hidden dim (H*D)
#define PW     512        // q|k|v|skip packed row width

// ---------------- static scratch (no allocs allowed) ----------------
__device__ float g_P[(size_t)NMAX * PW];      // packed projections q|k|v|s
__device__ float g_H0[(size_t)NMAX * HD];     // layer0 output (post relu)
__device__ float g_H1[(size_t)NMAX * HD];     // layer1 output (post relu)
__device__ int   g_deg[NMAX];
__device__ int   g_cnt[NMAX];
__device__ int   g_rowptr[NMAX + 1];
__device__ int   g_src[EMAX];
__device__ float g_attr[EMAX];
__device__ int   g_ghist[GMAX];
__device__ int   g_gstart[GMAX + 1];
__device__ float g_pool[GMAX * HD];

// ---------------- CSR build ----------------
__global__ void zero_kernel(int N) {
    int i = blockIdx.x * blockDim.x + threadIdx.x;
    if (i < N) { g_deg[i] = 0; g_cnt[i] = 0; }
    if (i < GMAX) g_ghist[i] = 0;
}

__global__ void hist_kernel(const int* __restrict__ dst,
                            const int* __restrict__ batch, int N, int E) {
    int i = blockIdx.x * blockDim.x + threadIdx.x;
    if (i < E) atomicAdd(&g_deg[dst[i]], 1);
    if (i < N) atomicAdd(&g_ghist[batch[i]], 1);
}

// single-block exclusive scan of g_deg -> g_rowptr; also g_ghist -> g_gstart
__global__ void scan_kernel(int N) {
    __shared__ int sums[1024];
    int t = threadIdx.x;
    int chunk = (N + 1023) >> 10;
    int lo = t * chunk;
    int hi = min(lo + chunk, N);
    int s = 0;
    for (int i = lo; i < hi; i++) s += g_deg[i];
    sums[t] = s;
    __syncthreads();
    for (int off = 1; off < 1024; off <<= 1) {
        int v = (t >= off) ? sums[t - off] : 0;
        __syncthreads();
        sums[t] += v;
        __syncthreads();
    }
    int run = sums[t] - s;   // exclusive prefix
    for (int i = lo; i < hi; i++) { g_rowptr[i] = run; run += g_deg[i]; }
    if (t == 1023) g_rowptr[N] = sums[1023];
    if (t == 0) {
        int r = 0;
        for (int g = 0; g < GMAX; g++) { g_gstart[g] = r; r += g_ghist[g]; }
        g_gstart[GMAX] = r;
    }
}

__global__ void scatter_kernel(const int* __restrict__ src,
                               const int* __restrict__ dst,
                               const float* __restrict__ attr, int E) {
    int i = blockIdx.x * blockDim.x + threadIdx.x;
    if (i >= E) return;
    int d = dst[i];
    int p = g_rowptr[d] + atomicAdd(&g_cnt[d], 1);
    g_src[p]  = src[i];
    g_attr[p] = attr[i];
}

// ---------------- layer-0 projections (in_ch = 2) ----------------
__global__ void proj0_kernel(const float* __restrict__ x,
                             const float* __restrict__ Wq, const float* __restrict__ bq,
                             const float* __restrict__ Wk, const float* __restrict__ bk,
                             const float* __restrict__ Wv, const float* __restrict__ bv,
                             const float* __restrict__ Ws, const float* __restrict__ bs,
                             int N) {
    int idx = blockIdx.x * blockDim.x + threadIdx.x;     // one float4 of P
    if (idx >= N * 128) return;
    int n  = idx >> 7;
    int c4 = idx & 127;            // float4 index within 512-wide row
    int sel = c4 >> 5;             // 0=q 1=k 2=v 3=skip
    int cc  = (c4 & 31) * 4;       // column within 128
    const float* W; const float* b;
    if (sel == 0)      { W = Wq; b = bq; }
    else if (sel == 1) { W = Wk; b = bk; }
    else if (sel == 2) { W = Wv; b = bv; }
    else               { W = Ws; b = bs; }
    float x0 = x[2 * n], x1 = x[2 * n + 1];
    float4 w0 = *(const float4*)(W + cc);        // W[0, cc..]
    float4 w1 = *(const float4*)(W + 128 + cc);  // W[1, cc..]
    float4 bb = *(const float4*)(b + cc);
    float4 r;
    r.x = fmaf(x0, w0.x, fmaf(x1, w1.x, bb.x));
    r.y = fmaf(x0, w0.y, fmaf(x1, w1.y, bb.y));
    r.z = fmaf(x0, w0.z, fmaf(x1, w1.z, bb.z));
    r.w = fmaf(x0, w0.w, fmaf(x1, w1.w, bb.w));
    ((float4*)g_P)[(size_t)n * 128 + c4] = r;
}

// ---------------- layer-1 projections: 3xTF32 tensor-core GEMM ----------------
#define SA 20     // A smem panel stride (16 + 4 pad)
#define SB 136    // B smem panel stride (128 + 8 pad)

__device__ __forceinline__ void split_tf32(float x, uint32_t& hi, uint32_t& lo) {
    uint32_t h;
    asm("cvt.rna.tf32.f32 %0, %1;" : "=r"(h) : "f"(x));
    float r = x - __uint_as_float(h);
    uint32_t l;
    asm("cvt.rna.tf32.f32 %0, %1;" : "=r"(l) : "f"(r));
    hi = h; lo = l;
}

__device__ __forceinline__ void mma8(float* c, const uint32_t* a, const uint32_t* b) {
    asm volatile(
        "mma.sync.aligned.m16n8k8.row.col.f32.tf32.tf32.f32 "
        "{%0,%1,%2,%3}, {%4,%5,%6,%7}, {%8,%9}, {%0,%1,%2,%3};"
        : "+f"(c[0]), "+f"(c[1]), "+f"(c[2]), "+f"(c[3])
        : "r"(a[0]), "r"(a[1]), "r"(a[2]), "r"(a[3]), "r"(b[0]), "r"(b[1]));
}

__global__ __launch_bounds__(256, 2) void gemm3_kernel(
    const float* __restrict__ Wq, const float* __restrict__ Wk,
    const float* __restrict__ Wv, const float* __restrict__ Ws,
    const float* __restrict__ bq, const float* __restrict__ bk,
    const float* __restrict__ bv, const float* __restrict__ bs) {
    __shared__ uint32_t AsH[128][SA];
    __shared__ uint32_t AsL[128][SA];
    __shared__ uint32_t BsH[16][SB];
    __shared__ uint32_t BsL[16][SB];

    const float* W; const float* bias;
    int sec = blockIdx.y;
    if (sec == 0)      { W = Wq; bias = bq; }
    else if (sec == 1) { W = Wk; bias = bk; }
    else if (sec == 2) { W = Wv; bias = bv; }
    else               { W = Ws; bias = bs; }

    int tid  = threadIdx.x;
    int warp = tid >> 5, lane = tid & 31;
    int g    = lane >> 2, tig = lane & 3;
    int wm   = warp >> 2, wn = warp & 3;         // 2 x 4 warp grid
    int blockM = blockIdx.x * 128;

    float acc[4][4][4];
#pragma unroll
    for (int mt = 0; mt < 4; mt++)
#pragma unroll
        for (int nt = 0; nt < 4; nt++)
#pragma unroll
            for (int c = 0; c < 4; c++) acc[mt][nt][c] = 0.f;

#pragma unroll 1
    for (int kp = 0; kp < 8; kp++) {
        int k0 = kp * 16;
        __syncthreads();
#pragma unroll
        for (int j = 0; j < 2; j++) {
            int pos = tid + 256 * j;
            int row = pos >> 2;
            int c4  = pos & 3;
            float4 v = *(const float4*)(g_H0 + (size_t)(blockM + row) * 128 + k0 + c4 * 4);
            uint4 h, l;
            split_tf32(v.x, h.x, l.x);
            split_tf32(v.y, h.y, l.y);
            split_tf32(v.z, h.z, l.z);
            split_tf32(v.w, h.w, l.w);
            *(uint4*)&AsH[row][c4 * 4] = h;
            *(uint4*)&AsL[row][c4 * 4] = l;
        }
#pragma unroll
        for (int j = 0; j < 2; j++) {
            int pos = tid + 256 * j;
            int row = pos >> 5;
            int c4  = pos & 31;
            float4 v = *(const float4*)(W + (size_t)(k0 + row) * 128 + c4 * 4);
            uint4 h, l;
            split_tf32(v.x, h.x, l.x);
            split_tf32(v.y, h.y, l.y);
            split_tf32(v.z, h.z, l.z);
            split_tf32(v.w, h.w, l.w);
            *(uint4*)&BsH[row][c4 * 4] = h;
            *(uint4*)&BsL[row][c4 * 4] = l;
        }
        __syncthreads();

#pragma unroll
        for (int ks = 0; ks < 2; ks++) {
            int kk = ks * 8;
            uint32_t bh[4][2], bl[4][2];
#pragma unroll
            for (int nt = 0; nt < 4; nt++) {
                int col = wn * 32 + nt * 8 + g;
                bh[nt][0] = BsH[kk + tig][col];
                bh[nt][1] = BsH[kk + tig + 4][col];
                bl[nt][0] = BsL[kk + tig][col];
                bl[nt][1] = BsL[kk + tig + 4][col];
            }
#pragma unroll
            for (int mt = 0; mt < 4; mt++) {
                int r0 = wm * 64 + mt * 16 + g;
                uint32_t ah[4], al[4];
                ah[0] = AsH[r0][kk + tig];
                ah[1] = AsH[r0 + 8][kk + tig];
                ah[2] = AsH[r0][kk + tig + 4];
                ah[3] = AsH[r0 + 8][kk + tig + 4];
                al[0] = AsL[r0][kk + tig];
                al[1] = AsL[r0 + 8][kk + tig];
                al[2] = AsL[r0][kk + tig + 4];
                al[3] = AsL[r0 + 8][kk + tig + 4];
#pragma unroll
                for (int nt = 0; nt < 4; nt++) {
                    mma8(acc[mt][nt], ah, bh[nt]);   // hi*hi
                    mma8(acc[mt][nt], ah, bl[nt]);   // hi*lo
                    mma8(acc[mt][nt], al, bh[nt]);   // lo*hi
                }
            }
        }
    }

    int secOff = sec * 128;
#pragma unroll
    for (int mt = 0; mt < 4; mt++) {
        int r0 = blockM + wm * 64 + mt * 16 + g;
#pragma unroll
        for (int nt = 0; nt < 4; nt++) {
            int cn = wn * 32 + nt * 8 + tig * 2;
            float b0 = bias[cn], b1 = bias[cn + 1];
            float2 v0 = make_float2(acc[mt][nt][0] + b0, acc[mt][nt][1] + b1);
            float2 v1 = make_float2(acc[mt][nt][2] + b0, acc[mt][nt][3] + b1);
            *(float2*)(g_P + (size_t)r0 * PW + secOff + cn)       = v0;
            *(float2*)(g_P + (size_t)(r0 + 8) * PW + secOff + cn) = v1;
        }
    }
}

// ---------------- edge attention: warp/node, dual-state online softmax ----------------
// P row layout (float4 units, 128 per row): q:0..31  k:32..63  v:64..95  s:96..127
__device__ __forceinline__ float dot_reduce16(float4 q, float4 k) {
    float part = q.x * k.x + q.y * k.y + q.z * k.z + q.w * k.w;
    part += __shfl_xor_sync(0xffffffffu, part, 8, 16);
    part += __shfl_xor_sync(0xffffffffu, part, 4, 16);
    part += __shfl_xor_sync(0xffffffffu, part, 2, 16);
    part += __shfl_xor_sync(0xffffffffu, part, 1, 16);
    return part * 0.125f;   // / sqrt(64)
}

__global__ void attn_kernel(const float* __restrict__ We, int which, int N) {
    int gt   = blockIdx.x * blockDim.x + threadIdx.x;
    int lane = threadIdx.x & 31;
    int n    = gt >> 5;
    if (n >= N) return;

    const float4* P4 = (const float4*)g_P;
    size_t base = (size_t)n * 128;
    float4 qv = __ldg(P4 + base + lane);
    float4 we = __ldg(((const float4*)We) + lane);

    // two independent online-softmax states
    float4 accA = make_float4(0.f, 0.f, 0.f, 0.f);
    float4 accB = make_float4(0.f, 0.f, 0.f, 0.f);
    float mA = -1e30f, mB = -1e30f;
    float dA = 0.f,    dB = 0.f;

    int beg = g_rowptr[n], end = g_rowptr[n + 1];
    int i = beg;
    for (; i + 1 < end; i += 2) {
        int   s0 = __ldg(g_src + i);
        int   s1 = __ldg(g_src + i + 1);
        float a0 = __ldg(g_attr + i);
        float a1 = __ldg(g_attr + i + 1);
        size_t sb0 = (size_t)s0 * 128;
        size_t sb1 = (size_t)s1 * 128;

        float4 k0 = __ldg(P4 + sb0 + 32 + lane);
        float4 k1 = __ldg(P4 + sb1 + 32 + lane);
        float4 v0 = __ldg(P4 + sb0 + 64 + lane);
        float4 v1 = __ldg(P4 + sb1 + 64 + lane);

        k0.x = fmaf(a0, we.x, k0.x); k0.y = fmaf(a0, we.y, k0.y);
        k0.z = fmaf(a0, we.z, k0.z); k0.w = fmaf(a0, we.w, k0.w);
        k1.x = fmaf(a1, we.x, k1.x); k1.y = fmaf(a1, we.y, k1.y);
        k1.z = fmaf(a1, we.z, k1.z); k1.w = fmaf(a1, we.w, k1.w);

        float l0 = dot_reduce16(qv, k0);
        float l1 = dot_reduce16(qv, k1);

        v0.x = fmaf(a0, we.x, v0.x); v0.y = fmaf(a0, we.y, v0.y);
        v0.z = fmaf(a0, we.z, v0.z); v0.w = fmaf(a0, we.w, v0.w);
        v1.x = fmaf(a1, we.x, v1.x); v1.y = fmaf(a1, we.y, v1.y);
        v1.z = fmaf(a1, we.z, v1.z); v1.w = fmaf(a1, we.w, v1.w);

        // state A <- edge0
        {
            float nm = fmaxf(mA, l0);
            float sc = __expf(mA - nm);
            float ex = __expf(l0 - nm);
            accA.x = fmaf(accA.x, sc, ex * v0.x);
            accA.y = fmaf(accA.y, sc, ex * v0.y);
            accA.z = fmaf(accA.z, sc, ex * v0.z);
            accA.w = fmaf(accA.w, sc, ex * v0.w);
            dA = fmaf(dA, sc, ex);
            mA = nm;
        }
        // state B <- edge1
        {
            float nm = fmaxf(mB, l1);
            float sc = __expf(mB - nm);
            float ex = __expf(l1 - nm);
            accB.x = fmaf(accB.x, sc, ex * v1.x);
            accB.y = fmaf(accB.y, sc, ex * v1.y);
            accB.z = fmaf(accB.z, sc, ex * v1.z);
            accB.w = fmaf(accB.w, sc, ex * v1.w);
            dB = fmaf(dB, sc, ex);
            mB = nm;
        }
    }
    if (i < end) {   // odd tail -> state A
        int   s0 = __ldg(g_src + i);
        float a0 = __ldg(g_attr + i);
        size_t sb0 = (size_t)s0 * 128;
        float4 k0 = __ldg(P4 + sb0 + 32 + lane);
        float4 v0 = __ldg(P4 + sb0 + 64 + lane);
        k0.x = fmaf(a0, we.x, k0.x); k0.y = fmaf(a0, we.y, k0.y);
        k0.z = fmaf(a0, we.z, k0.z); k0.w = fmaf(a0, we.w, k0.w);
        float l0 = dot_reduce16(qv, k0);
        v0.x = fmaf(a0, we.x, v0.x); v0.y = fmaf(a0, we.y, v0.y);
        v0.z = fmaf(a0, we.z, v0.z); v0.w = fmaf(a0, we.w, v0.w);
        float nm = fmaxf(mA, l0);
        float sc = __expf(mA - nm);
        float ex = __expf(l0 - nm);
        accA.x = fmaf(accA.x, sc, ex * v0.x);
        accA.y = fmaf(accA.y, sc, ex * v0.y);
        accA.z = fmaf(accA.z, sc, ex * v0.z);
        accA.w = fmaf(accA.w, sc, ex * v0.w);
        dA = fmaf(dA, sc, ex);
        mA = nm;
    }

    // exact merge of the two states
    float nm = fmaxf(mA, mB);
    float eA = __expf(mA - nm);
    float eB = __expf(mB - nm);
    float den = dA * eA + dB * eB;
    float4 acc;
    acc.x = accA.x * eA + accB.x * eB;
    acc.y = accA.y * eA + accB.y * eB;
    acc.z = accA.z * eA + accB.z * eB;
    acc.w = accA.w * eA + accB.w * eB;

    float inv = 1.f / (den + 1e-16f);
    float4 sk = __ldg(P4 + base + 96 + lane);
    float4 o;
    o.x = fmaxf(fmaf(acc.x, inv, sk.x), 0.f);
    o.y = fmaxf(fmaf(acc.y, inv, sk.y), 0.f);
    o.z = fmaxf(fmaf(acc.z, inv, sk.z), 0.f);
    o.w = fmaxf(fmaf(acc.w, inv, sk.w), 0.f);
    float* H = which ? g_H1 : g_H0;
    ((float4*)H)[(size_t)n * 32 + lane] = o;
}

// ---------------- graph mean pool (batch is sorted) ----------------
__global__ void pool_kernel() {
    int g = blockIdx.x;
    int t = threadIdx.x;
    int b0 = g_gstart[g], b1 = g_gstart[g + 1];
    float acc = 0.f;
#pragma unroll 4
    for (int n = b0; n < b1; n++) acc += g_H1[(size_t)n * HD + t];
    float c = (float)max(b1 - b0, 1);
    g_pool[g * HD + t] = acc / c;
}

// ---------------- classifier head ----------------
__global__ void classifier_kernel(const float* __restrict__ cW1, const float* __restrict__ cb1,
                                  const float* __restrict__ cW2, const float* __restrict__ cb2,
                                  float* __restrict__ out) {
    __shared__ float gs[HD];
    __shared__ float hid[HD];
    int g = blockIdx.x;
    int t = threadIdx.x;
    gs[t] = g_pool[g * HD + t];
    __syncthreads();
    float acc = cb1[t];
#pragma unroll 8
    for (int c = 0; c < HD; c++) acc = fmaf(gs[c], cW1[c * 128 + t], acc);
    hid[t] = fmaxf(acc, 0.f);
    __syncthreads();
    if (t < 30) {
        float o = cb2[t];
#pragma unroll 8
        for (int j = 0; j < HD; j++) o = fmaf(hid[j], cW2[j * 30 + t], o);
        out[g * 30 + t] = o;
    }
}

// ---------------- launch ----------------
extern "C" void kernel_launch(void* const* d_in, const int* in_sizes, int n_in,
                              void* d_out, int out_size) {
    const float* x      = (const float*)d_in[0];
    const int*   ei     = (const int*)d_in[1];
    const float* eattr  = (const float*)d_in[2];
    const int*   batch  = (const int*)d_in[3];
    const float* l0_Wq = (const float*)d_in[4];
    const float* l0_bq = (const float*)d_in[5];
    const float* l0_Wk = (const float*)d_in[6];
    const float* l0_bk = (const float*)d_in[7];
    const float* l0_Wv = (const float*)d_in[8];
    const float* l0_bv = (const float*)d_in[9];
    const float* l0_We = (const float*)d_in[10];
    const float* l0_Ws = (const float*)d_in[11];
    const float* l0_bs = (const float*)d_in[12];
    const float* l1_Wq = (const float*)d_in[13];
    const float* l1_bq = (const float*)d_in[14];
    const float* l1_Wk = (const float*)d_in[15];
    const float* l1_bk = (const float*)d_in[16];
    const float* l1_Wv = (const float*)d_in[17];
    const float* l1_bv = (const float*)d_in[18];
    const float* l1_We = (const float*)d_in[19];
    const float* l1_Ws = (const float*)d_in[20];
    const float* l1_bs = (const float*)d_in[21];
    const float* cW1   = (const float*)d_in[22];
    const float* cb1   = (const float*)d_in[23];
    const float* cW2   = (const float*)d_in[24];
    const float* cb2   = (const float*)d_in[25];
    float* out = (float*)d_out;

    int N = in_sizes[3];       // batch length = #nodes
    int E = in_sizes[2];       // edge_attr length = #edges
    const int* src = ei;
    const int* dst = ei + E;

    // CSR build (reused by both layers)
    zero_kernel<<<(N + 255) / 256, 256>>>(N);
    hist_kernel<<<(E + 255) / 256, 256>>>(dst, batch, N, E);
    scan_kernel<<<1, 1024>>>(N);
    scatter_kernel<<<(E + 255) / 256, 256>>>(src, dst, eattr, E);

    // layer 0
    proj0_kernel<<<(N * 128 + 255) / 256, 256>>>(x, l0_Wq, l0_bq, l0_Wk, l0_bk,
                                                 l0_Wv, l0_bv, l0_Ws, l0_bs, N);
    attn_kernel<<<(N * 32 + 255) / 256, 256>>>(l0_We, 0, N);

    // layer 1 projections: fused 3xTF32 tensor-core GEMM, all 4 weights
    dim3 ggrid((N + 127) / 128, 4);
    gemm3_kernel<<<ggrid, 256>>>(l1_Wq, l1_Wk, l1_Wv, l1_Ws,
                                 l1_bq, l1_bk, l1_bv, l1_bs);

    attn_kernel<<<(N * 32 + 255) / 256, 256>>>(l1_We, 1, N);

    // pool + head
    pool_kernel<<<GMAX, HD>>>();
    classifier_kernel<<<GMAX, HD>>>(cW1, cb1, cW2, cb2, out);
}